// round 10
// baseline (speedup 1.0000x reference)
#include <cuda_runtime.h>
#include <cuda_bf16.h>
#include <cstdint>
#include <cstddef>

#define NN 4096
#define FD 256
#define HD 256
#define KG 3
#define G4 1024
#define TST 5

typedef __nv_bfloat16 bf16;
typedef __nv_bfloat162 bf162;

// ---------------- scratch (device globals) ----------------
static __device__ __align__(16) bf16 g_bx[NN*FD];
static __device__ __align__(16) bf16 g_bgw[KG*FD*HD];
static __device__ __align__(16) uint8_t g_wihp8[KG*G4*HD];          // fp8(16*w), gate-permuted
static __device__ __align__(16) uint8_t g_whhp8[KG*G4*HD];          // fp8(16*w), gate-permuted
static __device__ __align__(16) uint8_t g_fcw8[KG*FD*HD];           // fp8(16*w)
static __device__ __align__(16) uint8_t g_a8[(size_t)KG*NN*NN];     // fp8 adjacency planes (+I), exact
static __device__ __align__(16) uint8_t g_sT8[(size_t)KG*HD*NN];    // fp8(64*dinv_j*xw), TRANSPOSED [h][j]
static __device__ __align__(16) uint8_t g_gnn8[(size_t)KG*NN*HD];   // fp8 gnn out
static __device__ __align__(16) uint8_t g_h8[(size_t)KG*NN*HD];     // fp8 lstm h
static __device__ __align__(16) bf16 g_xtp16[(size_t)KG*NN*G4];     // x-part of gates, permuted, bf16

static __device__ float g_dinv[KG*NN];
static __device__ float g_bcomb[KG*G4];                              // b_ih + b_hh, permuted
static __device__ float g_c[(size_t)KG*NN*HD];
static __device__ float g_delta[(size_t)KG*NN*FD];

// ---------------- helpers ----------------
__device__ __forceinline__ float sigf(float x){
    x = fminf(fmaxf(x, -30.f), 30.f);
    return __fdividef(1.f, 1.f + __expf(-x));
}
__device__ __forceinline__ float tanhf_(float x){
    x = fminf(fmaxf(x, -15.f), 15.f);
    float e = __expf(2.f*x);
    return __fdividef(e - 1.f, e + 1.f);
}
__device__ __forceinline__ uint16_t f2e4m3x2(float lo, float hi){
    uint16_t r; asm("cvt.rn.satfinite.e4m3x2.f32 %0, %1, %2;" : "=h"(r) : "f"(hi), "f"(lo));
    return r;   // byte0 = lo, byte1 = hi
}
__device__ __forceinline__ uint8_t f2e4m3(float v){
    uint16_t r; asm("cvt.rn.satfinite.e4m3x2.f32 %0, %1, %2;" : "=h"(r) : "f"(0.f), "f"(v));
    return (uint8_t)r;
}
__device__ __forceinline__ void mma_f8(float* c, const uint32_t* a, const uint32_t* b){
    asm volatile(
        "mma.sync.aligned.m16n8k32.row.col.f32.e4m3.e4m3.f32 "
        "{%0,%1,%2,%3}, {%4,%5,%6,%7}, {%8,%9}, {%0,%1,%2,%3};"
        : "+f"(c[0]), "+f"(c[1]), "+f"(c[2]), "+f"(c[3])
        : "r"(a[0]), "r"(a[1]), "r"(a[2]), "r"(a[3]), "r"(b[0]), "r"(b[1]));
}
__device__ __forceinline__ void mma16816(float* c, const uint32_t* a, const uint32_t* b){
    asm volatile(
        "mma.sync.aligned.m16n8k16.row.col.f32.bf16.bf16.f32 "
        "{%0,%1,%2,%3}, {%4,%5,%6,%7}, {%8,%9}, {%0,%1,%2,%3};"
        : "+f"(c[0]), "+f"(c[1]), "+f"(c[2]), "+f"(c[3])
        : "r"(a[0]), "r"(a[1]), "r"(a[2]), "r"(a[3]), "r"(b[0]), "r"(b[1]));
}
__device__ __forceinline__ void ldsm4(uint32_t& r0, uint32_t& r1, uint32_t& r2, uint32_t& r3, uint32_t a){
    asm volatile("ldmatrix.sync.aligned.m8n8.x4.shared.b16 {%0,%1,%2,%3}, [%4];"
        : "=r"(r0), "=r"(r1), "=r"(r2), "=r"(r3) : "r"(a));
}
__device__ __forceinline__ void ldsm4t(uint32_t& r0, uint32_t& r1, uint32_t& r2, uint32_t& r3, uint32_t a){
    asm volatile("ldmatrix.sync.aligned.m8n8.x4.trans.shared.b16 {%0,%1,%2,%3}, [%4];"
        : "=r"(r0), "=r"(r1), "=r"(r2), "=r"(r3) : "r"(a));
}
__device__ __forceinline__ void cpasync16(uint32_t dst, const void* src){
    asm volatile("cp.async.cg.shared.global [%0], [%1], 16;\n" :: "r"(dst), "l"(src));
}
#define SWZ(off) ((off) ^ (((off) >> 3) & 0x70))

// ---------------- prep: conversions + gate permutation ----------------
// permuted gate index: cp = (u>>3)*32 + gate*8 + (u&7)
__global__ void __launch_bounds__(256) prep_conv(
    const float* __restrict__ x, const float* __restrict__ gw,
    const float* __restrict__ wih, const float* __restrict__ whh,
    const float* __restrict__ bih, const float* __restrict__ bhh,
    const float* __restrict__ fcw)
{
    int i = blockIdx.x*blockDim.x + threadIdx.x;
    int stride = gridDim.x*blockDim.x;
    for (int t = i; t < NN*FD; t += stride)    g_bx[t]   = __float2bfloat16_rn(x[t]);
    for (int t = i; t < KG*FD*HD; t += stride) g_bgw[t]  = __float2bfloat16_rn(gw[t]);
    for (int t = i; t < KG*FD*HD; t += stride) g_fcw8[t] = f2e4m3(16.f*fcw[t]);
    for (int t = i; t < KG*G4*HD; t += stride){
        int k = t / (G4*HD);
        int rem = t - k*(G4*HD);
        int cp = rem >> 8, h = rem & 255;
        int gate = (cp >> 3) & 3;
        int u = ((cp >> 5) << 3) | (cp & 7);
        int orig = k*G4*HD + (gate*256 + u)*HD + h;
        g_wihp8[t] = f2e4m3(16.f*wih[orig]);
        g_whhp8[t] = f2e4m3(16.f*whh[orig]);
    }
    for (int t = i; t < KG*G4; t += stride){
        int k = t >> 10, cp = t & 1023;
        int gate = (cp >> 3) & 3;
        int u = ((cp >> 5) << 3) | (cp & 7);
        g_bcomb[t] = bih[k*G4 + gate*256 + u] + bhh[k*G4 + gate*256 + u];
    }
}

// ---------------- adj_deg: fp8 planes (+I) + dinv (critical path) ----------------
__global__ void __launch_bounds__(256) adj_deg(const int* __restrict__ adj)
{
    int row = blockIdx.x;
    const int4* src = reinterpret_cast<const int4*>(adj + (size_t)row*NN*KG);
    int c0 = 0, c1 = 0, c2 = 0;
    #pragma unroll
    for (int it = 0; it < 4; it++){
        int jg = threadIdx.x + it*256;               // group of 4 j's
        int4 v0 = src[jg*3+0];
        int4 v1 = src[jg*3+1];
        int4 v2 = src[jg*3+2];
        // e4m3: 1.0f = 0x38
        uint32_t q0 = (v0.x?0x38u:0u) | ((v0.w?0x38u:0u)<<8) | ((v1.z?0x38u:0u)<<16) | ((v2.y?0x38u:0u)<<24);
        uint32_t q1 = (v0.y?0x38u:0u) | ((v1.x?0x38u:0u)<<8) | ((v1.w?0x38u:0u)<<16) | ((v2.z?0x38u:0u)<<24);
        uint32_t q2 = (v0.z?0x38u:0u) | ((v1.y?0x38u:0u)<<8) | ((v2.x?0x38u:0u)<<16) | ((v2.w?0x38u:0u)<<24);
        size_t base = (size_t)row*NN + jg*4;
        *reinterpret_cast<uint32_t*>(&g_a8[base])                   = q0;
        *reinterpret_cast<uint32_t*>(&g_a8[(size_t)NN*NN + base])   = q1;
        *reinterpret_cast<uint32_t*>(&g_a8[(size_t)2*NN*NN + base]) = q2;
        c0 += (v0.x?1:0) + (v0.w?1:0) + (v1.z?1:0) + (v2.y?1:0);
        c1 += (v0.y?1:0) + (v1.x?1:0) + (v1.w?1:0) + (v2.z?1:0);
        c2 += (v0.z?1:0) + (v1.y?1:0) + (v2.x?1:0) + (v2.w?1:0);
    }
    __shared__ int sm[3];
    if (threadIdx.x < 3) sm[threadIdx.x] = 0;
    __syncthreads();
    c0 = __reduce_add_sync(0xffffffffu, c0);
    c1 = __reduce_add_sync(0xffffffffu, c1);
    c2 = __reduce_add_sync(0xffffffffu, c2);
    if ((threadIdx.x & 31) == 0){
        atomicAdd(&sm[0], c0); atomicAdd(&sm[1], c1); atomicAdd(&sm[2], c2);
    }
    __syncthreads();
    if (threadIdx.x < 3){
        // self-loop: 0->1.0(0x38), 1->2.0(0x40); exact in e4m3
        size_t d = (size_t)threadIdx.x*NN*NN + (size_t)row*NN + row;
        g_a8[d] = (g_a8[d] == 0x38) ? 0x40 : 0x38;
        float deg = (float)(sm[threadIdx.x] + 1);
        g_dinv[threadIdx.x*NN + row] = rsqrtf(deg);
    }
}

// ---------------- adj_out: float passthrough (forked stream; no consumers) ----------------
__global__ void __launch_bounds__(256) adj_out(const int* __restrict__ adj,
                                               float* __restrict__ out_adj)
{
    const int4* src = reinterpret_cast<const int4*>(adj);
    float4* dst = reinterpret_cast<float4*>(out_adj);
    int i = blockIdx.x*256 + threadIdx.x;
    int stride = gridDim.x*256;
    const int total = NN*NN*KG/4;
    for (int t = i; t < total; t += stride){
        int4 v = src[t];
        dst[t] = make_float4((float)v.x, (float)v.y, (float)v.z, (float)v.w);
    }
}

// ---------------- XW GEMM (bf16): s = dinv*x@gnn_w, stored TRANSPOSED as fp8(64*s) ----------------
__global__ void __launch_bounds__(256, 2) gemm_xw()
{
    __shared__ bf16 As[2][128*64];
    __shared__ bf16 Bs[2][64*64];
    int n0 = blockIdx.x*64, m0 = blockIdx.y*128, kb = blockIdx.z;
    const bf16* A = g_bx;
    const bf16* B = g_bgw + (size_t)kb*FD*HD;

    int tid = threadIdx.x, lane = tid & 31, wid = tid >> 5;
    int wm = wid & 3, wn = wid >> 2;
    uint32_t asB[2], bsB[2];
    asB[0] = (uint32_t)__cvta_generic_to_shared(&As[0][0]);
    asB[1] = (uint32_t)__cvta_generic_to_shared(&As[1][0]);
    bsB[0] = (uint32_t)__cvta_generic_to_shared(&Bs[0][0]);
    bsB[1] = (uint32_t)__cvta_generic_to_shared(&Bs[1][0]);

    float acc[2][4][4];
    #pragma unroll
    for (int a = 0; a < 2; a++)
        #pragma unroll
        for (int b = 0; b < 4; b++)
            #pragma unroll
            for (int e = 0; e < 4; e++) acc[a][b][e] = 0.f;

    auto load_tile = [&](int kt, int s){
        #pragma unroll
        for (int i = 0; i < 4; i++){
            int idx = tid + i*256;
            int row = idx >> 3, c = idx & 7;
            cpasync16(asB[s] + SWZ(row*128 + c*16), A + (size_t)(m0+row)*HD + kt*64 + c*8);
        }
        #pragma unroll
        for (int i = 0; i < 2; i++){
            int idx = tid + i*256;
            int row = idx >> 3, c = idx & 7;
            cpasync16(bsB[s] + SWZ(row*128 + c*16), B + (size_t)(kt*64 + row)*HD + n0 + c*8);
        }
        asm volatile("cp.async.commit_group;\n" ::: "memory");
    };

    load_tile(0, 0);
    int lr = lane & 15, lc = lane >> 4;
    for (int kt = 0; kt < 4; kt++){
        if (kt + 1 < 4){
            load_tile(kt+1, (kt+1)&1);
            asm volatile("cp.async.wait_group 1;\n" ::: "memory");
        } else {
            asm volatile("cp.async.wait_group 0;\n" ::: "memory");
        }
        __syncthreads();
        int s = kt & 1;
        #pragma unroll
        for (int k16 = 0; k16 < 4; k16++){
            uint32_t a[2][4];
            #pragma unroll
            for (int mt = 0; mt < 2; mt++){
                int row = wm*32 + mt*16 + lr;
                ldsm4(a[mt][0], a[mt][1], a[mt][2], a[mt][3], asB[s] + SWZ(row*128 + k16*32 + lc*16));
            }
            uint32_t b[4][2];
            #pragma unroll
            for (int p = 0; p < 2; p++){
                uint32_t r0, r1, r2, r3;
                int row = k16*16 + lr;
                ldsm4t(r0, r1, r2, r3, bsB[s] + SWZ(row*128 + (wn*32 + p*16 + lc*8)*2));
                b[p*2  ][0] = r0; b[p*2  ][1] = r1;
                b[p*2+1][0] = r2; b[p*2+1][1] = r3;
            }
            #pragma unroll
            for (int mt = 0; mt < 2; mt++)
                #pragma unroll
                for (int nt = 0; nt < 4; nt++)
                    mma16816(acc[mt][nt], a[mt], b[nt]);
        }
        __syncthreads();
    }

    int g = lane >> 2, t4 = lane & 3;
    #pragma unroll
    for (int mt = 0; mt < 2; mt++)
        #pragma unroll
        for (int nt = 0; nt < 4; nt++)
            #pragma unroll
            for (int rh = 0; rh < 2; rh++){
                int r = m0 + wm*32 + mt*16 + g + rh*8;
                int c = n0 + wn*32 + nt*8 + t4*2;
                float sc = 64.f * g_dinv[kb*NN + r];
                size_t tb = (size_t)kb*HD*NN;
                g_sT8[tb + (size_t)c*NN + r]     = f2e4m3(sc*acc[mt][nt][rh*2+0]);
                g_sT8[tb + (size_t)(c+1)*NN + r] = f2e4m3(sc*acc[mt][nt][rh*2+1]);
            }
}

// ---------------- fp8 epilogues ----------------
struct EpiGCN {
    const float* gb;
    __device__ void operator()(int k, int r, int c, float v0, float v1) const {
        float di = g_dinv[k*NN + r] * (1.f/64.f);
        size_t i = ((size_t)k*NN + r)*HD + c;
        *reinterpret_cast<uint16_t*>(&g_gnn8[i]) =
            f2e4m3x2(di*v0 + gb[k*HD + c], di*v1 + gb[k*HD + c + 1]);
    }
};
struct EpiFC {
    const float* fcb;
    __device__ void operator()(int k, int r, int c, float v0, float v1) const {
        size_t i = ((size_t)k*NN + r)*FD + c;
        g_delta[i]   = tanhf_(v0*(1.f/16.f) + fcb[k*FD + c]);
        g_delta[i+1] = tanhf_(v1*(1.f/16.f) + fcb[k*FD + c + 1]);
    }
};

// ---------------- fp8 GEMM: BM=128, BN=64, BK=128 bytes, double-buffered ----------------
// A row-major [M][KD] fp8; B n-major [NC][KD] fp8 (row = output col, bytes = k).
template<int KD, int NC, bool GORD, class Epi>
__global__ void __launch_bounds__(256, 2) gemm_f8(int a_sel, int b_sel, Epi epi)
{
    __shared__ uint8_t As[2][128*128];
    __shared__ uint8_t Bs[2][64*128];

    int n0, m0, kb;
    if (GORD){ n0 = blockIdx.x*64; kb = blockIdx.y; m0 = blockIdx.z*128; }
    else     { n0 = blockIdx.x*64; m0 = blockIdx.y*128; kb = blockIdx.z; }

    const uint8_t* A = (a_sel == 0) ? g_a8 + (size_t)kb*NN*NN
                                    : g_h8 + (size_t)kb*NN*HD;
    const uint8_t* B = (b_sel == 0) ? g_sT8 + (size_t)kb*HD*NN
                                    : g_fcw8 + (size_t)kb*FD*HD;

    int tid = threadIdx.x, lane = tid & 31, wid = tid >> 5;
    int wm = wid & 3, wn = wid >> 2;
    uint32_t asB[2], bsB[2];
    asB[0] = (uint32_t)__cvta_generic_to_shared(&As[0][0]);
    asB[1] = (uint32_t)__cvta_generic_to_shared(&As[1][0]);
    bsB[0] = (uint32_t)__cvta_generic_to_shared(&Bs[0][0]);
    bsB[1] = (uint32_t)__cvta_generic_to_shared(&Bs[1][0]);

    float acc[2][4][4];
    #pragma unroll
    for (int a = 0; a < 2; a++)
        #pragma unroll
        for (int b = 0; b < 4; b++)
            #pragma unroll
            for (int e = 0; e < 4; e++) acc[a][b][e] = 0.f;

    constexpr int KT = KD/128;

    // hoisted cp.async addressing (64-bit math out of the k-loop)
    const uint8_t* ap[4]; uint32_t ao[4];
    #pragma unroll
    for (int i = 0; i < 4; i++){
        int idx = tid + i*256;
        int row = idx >> 3, c = idx & 7;
        ap[i] = A + (size_t)(m0+row)*KD + c*16;
        ao[i] = SWZ(row*128 + c*16);
    }
    const uint8_t* bp[2]; uint32_t bo[2];
    #pragma unroll
    for (int i = 0; i < 2; i++){
        int idx = tid + i*256;
        int row = idx >> 3, c = idx & 7;
        bp[i] = B + (size_t)(n0+row)*KD + c*16;
        bo[i] = SWZ(row*128 + c*16);
    }

    auto load_tile = [&](int kt, int s){
        #pragma unroll
        for (int i = 0; i < 4; i++) cpasync16(asB[s] + ao[i], ap[i] + kt*128);
        #pragma unroll
        for (int i = 0; i < 2; i++) cpasync16(bsB[s] + bo[i], bp[i] + kt*128);
        asm volatile("cp.async.commit_group;\n" ::: "memory");
    };

    load_tile(0, 0);
    int lr = lane & 15, lc = lane >> 4;
    for (int kt = 0; kt < KT; kt++){
        if (kt + 1 < KT){
            load_tile(kt+1, (kt+1)&1);
            asm volatile("cp.async.wait_group 1;\n" ::: "memory");
        } else {
            asm volatile("cp.async.wait_group 0;\n" ::: "memory");
        }
        __syncthreads();
        int s = kt & 1;
        #pragma unroll
        for (int c32 = 0; c32 < 4; c32++){
            uint32_t a[2][4];
            #pragma unroll
            for (int mt = 0; mt < 2; mt++){
                int row = wm*32 + mt*16 + lr;
                ldsm4(a[mt][0], a[mt][1], a[mt][2], a[mt][3], asB[s] + SWZ(row*128 + c32*32 + lc*16));
            }
            uint32_t b[4][2];
            #pragma unroll
            for (int p = 0; p < 2; p++){
                uint32_t r0, r1, r2, r3;
                int row = wn*32 + p*16 + lr;
                ldsm4(r0, r1, r2, r3, bsB[s] + SWZ(row*128 + c32*32 + lc*16));
                b[p*2  ][0] = r0; b[p*2  ][1] = r2;
                b[p*2+1][0] = r1; b[p*2+1][1] = r3;
            }
            #pragma unroll
            for (int mt = 0; mt < 2; mt++)
                #pragma unroll
                for (int nt = 0; nt < 4; nt++)
                    mma_f8(acc[mt][nt], a[mt], b[nt]);
        }
        __syncthreads();
    }

    int g = lane >> 2, t4 = lane & 3;
    #pragma unroll
    for (int mt = 0; mt < 2; mt++)
        #pragma unroll
        for (int nt = 0; nt < 4; nt++){
            int r = m0 + wm*32 + mt*16 + g;
            int c = n0 + wn*32 + nt*8 + t4*2;
            epi(kb, r,     c, acc[mt][nt][0], acc[mt][nt][1]);
            epi(kb, r + 8, c, acc[mt][nt][2], acc[mt][nt][3]);
        }
}

// ---------------- fused fp8 LSTM GEMM + pointwise ----------------
template<bool FIRST>
__global__ void __launch_bounds__(256, 2) gemm_lstm()
{
    __shared__ uint8_t As[2][128*128];
    __shared__ uint8_t Bs[2][64*128];

    int n0 = blockIdx.x*64, m0 = blockIdx.y*128, kb = blockIdx.z;

    const uint8_t* A = (FIRST ? g_gnn8 : g_h8) + (size_t)kb*NN*HD;
    const uint8_t* B = (FIRST ? g_wihp8 : g_whhp8) + (size_t)kb*G4*HD;

    int tid = threadIdx.x, lane = tid & 31, wid = tid >> 5;
    int wm = wid & 3, wn = wid >> 2;
    uint32_t asB[2], bsB[2];
    asB[0] = (uint32_t)__cvta_generic_to_shared(&As[0][0]);
    asB[1] = (uint32_t)__cvta_generic_to_shared(&As[1][0]);
    bsB[0] = (uint32_t)__cvta_generic_to_shared(&Bs[0][0]);
    bsB[1] = (uint32_t)__cvta_generic_to_shared(&Bs[1][0]);

    float acc[2][4][4];
    #pragma unroll
    for (int a = 0; a < 2; a++)
        #pragma unroll
        for (int b = 0; b < 4; b++)
            #pragma unroll
            for (int e = 0; e < 4; e++) acc[a][b][e] = 0.f;

    auto load_tile = [&](int kt, int s){
        #pragma unroll
        for (int i = 0; i < 4; i++){
            int idx = tid + i*256;
            int row = idx >> 3, c = idx & 7;
            cpasync16(asB[s] + SWZ(row*128 + c*16), A + (size_t)(m0+row)*HD + kt*128 + c*16);
        }
        #pragma unroll
        for (int i = 0; i < 2; i++){
            int idx = tid + i*256;
            int row = idx >> 3, c = idx & 7;
            cpasync16(bsB[s] + SWZ(row*128 + c*16), B + (size_t)(n0+row)*HD + kt*128 + c*16);
        }
        asm volatile("cp.async.commit_group;\n" ::: "memory");
    };

    load_tile(0, 0);
    int lr = lane & 15, lc = lane >> 4;
    #pragma unroll
    for (int kt = 0; kt < 2; kt++){
        if (kt == 0){
            load_tile(1, 1);
            asm volatile("cp.async.wait_group 1;\n" ::: "memory");
        } else {
            asm volatile("cp.async.wait_group 0;\n" ::: "memory");
        }
        __syncthreads();
        int s = kt & 1;
        #pragma unroll
        for (int c32 = 0; c32 < 4; c32++){
            uint32_t a[2][4];
            #pragma unroll
            for (int mt = 0; mt < 2; mt++){
                int row = wm*32 + mt*16 + lr;
                ldsm4(a[mt][0], a[mt][1], a[mt][2], a[mt][3], asB[s] + SWZ(row*128 + c32*32 + lc*16));
            }
            uint32_t b[4][2];
            #pragma unroll
            for (int p = 0; p < 2; p++){
                uint32_t r0, r1, r2, r3;
                int row = wn*32 + p*16 + lr;
                ldsm4(r0, r1, r2, r3, bsB[s] + SWZ(row*128 + c32*32 + lc*16));
                b[p*2  ][0] = r0; b[p*2  ][1] = r2;
                b[p*2+1][0] = r1; b[p*2+1][1] = r3;
            }
            #pragma unroll
            for (int mt = 0; mt < 2; mt++)
                #pragma unroll
                for (int nt = 0; nt < 4; nt++)
                    mma_f8(acc[mt][nt], a[mt], b[nt]);
        }
        __syncthreads();
    }

    // ---- fused epilogue: gates -> (c, h) ----
    int g = lane >> 2, t4 = lane & 3;
    int group = (n0 + wn*32) >> 5;
    int ubase = group*8 + t4*2;                 // unit pair (ubase, ubase+1)
    #pragma unroll
    for (int mt = 0; mt < 2; mt++){
        #pragma unroll
        for (int rh = 0; rh < 2; rh++){
            int rr = m0 + wm*32 + mt*16 + g + rh*8;
            size_t xrow = ((size_t)kb*NN + rr)*G4 + n0 + wn*32 + t4*2;
            float gv[4][2];                     // [gate][unit01]
            #pragma unroll
            for (int nt = 0; nt < 4; nt++){
                float v0 = acc[mt][nt][rh*2+0] * (1.f/16.f);
                float v1 = acc[mt][nt][rh*2+1] * (1.f/16.f);
                if (FIRST){
                    const float2 bb = *reinterpret_cast<const float2*>(
                        &g_bcomb[kb*G4 + n0 + wn*32 + nt*8 + t4*2]);
                    v0 += bb.x; v1 += bb.y;
                    *reinterpret_cast<bf162*>(&g_xtp16[xrow + nt*8]) =
                        __floats2bfloat162_rn(v0, v1);
                } else {
                    bf162 xp = *reinterpret_cast<const bf162*>(&g_xtp16[xrow + nt*8]);
                    v0 += __bfloat162float(xp.x);
                    v1 += __bfloat162float(xp.y);
                }
                gv[nt][0] = v0; gv[nt][1] = v1;
            }
            size_t ci = ((size_t)kb*NN + rr)*HD + ubase;
            float c0_old = 0.f, c1_old = 0.f;
            if (!FIRST){
                float2 co = *reinterpret_cast<const float2*>(&g_c[ci]);
                c0_old = co.x; c1_old = co.y;
            }
            float cn0 = sigf(gv[1][0])*c0_old + sigf(gv[0][0])*tanhf_(gv[2][0]);
            float cn1 = sigf(gv[1][1])*c1_old + sigf(gv[0][1])*tanhf_(gv[2][1]);
            float hn0 = sigf(gv[3][0])*tanhf_(cn0);
            float hn1 = sigf(gv[3][1])*tanhf_(cn1);
            *reinterpret_cast<float2*>(&g_c[ci]) = make_float2(cn0, cn1);
            *reinterpret_cast<uint16_t*>(&g_h8[ci]) = f2e4m3x2(hn0, hn1);
        }
    }
}

// ---------------- final: pred + res_z_bar ----------------
__global__ void __launch_bounds__(256) final_out(const float* __restrict__ x,
                                                 float* __restrict__ out)
{
    int idx = blockIdx.x*256 + threadIdx.x;   // over NN*FD
    int f = idx & 255;
    bool sl = (f >= 10) && (f < FD - 3);      // START=10, F_DIM-END=253
    float xv = x[idx];
    float d0 = g_delta[idx];
    float d1 = g_delta[(size_t)NN*FD + idx];
    float d2 = g_delta[(size_t)2*NN*FD + idx];
    float z0 = xv + d0, z1 = xv + d1, z2 = xv + d2;
    if (sl){ z0 = sigf(z0); z1 = sigf(z1); z2 = sigf(z2); }
    size_t zb = (size_t)NN*FD + (size_t)idx*3;
    out[zb + 0] = z0; out[zb + 1] = z1; out[zb + 2] = z2;
    float dm = (d0 + d1 + d2) * (1.f/3.f);
    float p = xv + dm;
    if (sl) p = sigf(p);
    out[idx] = p;
}

// ---------------- stream/event resources (created once, first call is uncaptured) ----------------
struct AuxRes {
    cudaStream_t s1, s2;
    cudaEvent_t e_root, e_prep, e_adj;
    AuxRes(){
        cudaStreamCreateWithFlags(&s1, cudaStreamNonBlocking);
        cudaStreamCreateWithFlags(&s2, cudaStreamNonBlocking);
        cudaEventCreateWithFlags(&e_root, cudaEventDisableTiming);
        cudaEventCreateWithFlags(&e_prep, cudaEventDisableTiming);
        cudaEventCreateWithFlags(&e_adj,  cudaEventDisableTiming);
    }
};

// ---------------- launch ----------------
extern "C" void kernel_launch(void* const* d_in, const int* in_sizes, int n_in,
                              void* d_out, int out_size)
{
    const float* x     = (const float*)d_in[0];
    const float* gnn_w = (const float*)d_in[1];
    const float* gnn_b = (const float*)d_in[2];
    const float* w_ih  = (const float*)d_in[3];
    const float* w_hh  = (const float*)d_in[4];
    const float* b_ih  = (const float*)d_in[5];
    const float* b_hh  = (const float*)d_in[6];
    const float* fc_w  = (const float*)d_in[7];
    const float* fc_b  = (const float*)d_in[8];
    const int*   adj   = (const int*)d_in[9];
    float* out = (float*)d_out;

    (void)in_sizes; (void)n_in; (void)out_size;

    static AuxRes R;   // one-time resource creation (first call precedes capture)

    // fork: root event on the (capturing) legacy stream
    cudaEventRecord(R.e_root, 0);
    cudaStreamWaitEvent(R.s1, R.e_root, 0);
    cudaStreamWaitEvent(R.s2, R.e_root, 0);

    // s1: adj float passthrough (201 MB write; no consumers — overlaps the GEMM chain)
    adj_out<<<4096, 256, 0, R.s1>>>(adj, out + (size_t)NN*FD*(1 + KG));
    // s2: weight/x conversions (independent of adj)
    prep_conv<<<512, 256, 0, R.s2>>>(x, gnn_w, w_ih, w_hh, b_ih, b_hh, fc_w);
    cudaEventRecord(R.e_prep, R.s2);

    // main stream: fp8 planes + dinv (needed by everything downstream)
    adj_deg<<<NN, 256>>>(adj);

    // join prep before the GEMM chain
    cudaStreamWaitEvent(0, R.e_prep, 0);

    // sT8[h][j] = fp8(64 * dinv_j * (x @ gnn_w)[j][h])   (bf16 GEMM)
    gemm_xw<<<dim3(4, 32, 3), 256>>>();
    // gnn_out[k] = dinv_i * ((A+I) @ s)/64 + b           (fp8 GEMM, grid n,k,m for L2 A reuse)
    gemm_f8<4096, 256, true, EpiGCN><<<dim3(4, 3, 32), 256>>>(0, 0, EpiGCN{gnn_b});
    // xtp = gnn @ (16 Wp_ih)^T /16 + b, fused LSTM step 1
    gemm_lstm<true><<<dim3(16, 32, 3), 256>>>();
    // steps 2..5: gates = h @ (16 Wp_hh)^T /16 + xtp, fused pointwise
    for (int t = 1; t < TST; t++)
        gemm_lstm<false><<<dim3(16, 32, 3), 256>>>();
    // delta = tanh(h @ (16 fc_w)^T /16 + fc_b)
    gemm_f8<256, 256, false, EpiFC><<<dim3(4, 32, 3), 256>>>(1, 1, EpiFC{fc_b});
    final_out<<<NN*FD/256, 256>>>(x, out);

    // join the adj_out fork before capture ends
    cudaEventRecord(R.e_adj, R.s1);
    cudaStreamWaitEvent(0, R.e_adj, 0);
}

// round 12
// speedup vs baseline: 1.0731x; 1.0731x over previous
#include <cuda_runtime.h>
#include <cuda_bf16.h>
#include <cstdint>
#include <cstddef>

#define NN 4096
#define FD 256
#define HD 256
#define KG 3
#define G4 1024
#define TST 5

typedef __nv_bfloat16 bf16;
typedef __nv_bfloat162 bf162;

// ---------------- scratch (device globals) ----------------
static __device__ __align__(16) bf16 g_bx[NN*FD];
static __device__ __align__(16) bf16 g_bgw[KG*FD*HD];
static __device__ __align__(16) uint8_t g_wihp8[KG*G4*HD];          // fp8(16*w), gate-permuted
static __device__ __align__(16) uint8_t g_whhp8[KG*G4*HD];          // fp8(16*w), gate-permuted
static __device__ __align__(16) uint8_t g_fcw8[KG*FD*HD];           // fp8(16*w)
static __device__ __align__(16) uint8_t g_a8[(size_t)KG*NN*NN];     // fp8 adjacency planes (+I), exact
static __device__ __align__(16) uint8_t g_sT8[(size_t)KG*HD*NN];    // fp8(64*dinv_j*xw), TRANSPOSED [h][j]
static __device__ __align__(16) uint8_t g_gnn8[(size_t)KG*NN*HD];   // fp8 gnn out
static __device__ __align__(16) uint8_t g_h8[(size_t)KG*NN*HD];     // fp8 lstm h
static __device__ __align__(16) bf16 g_xtp16[(size_t)KG*NN*G4];     // x-part of gates, permuted, bf16

static __device__ float g_dinv[KG*NN];
static __device__ float g_bcomb[KG*G4];                              // b_ih + b_hh, permuted
static __device__ float g_c[(size_t)KG*NN*HD];
static __device__ float g_delta[(size_t)KG*NN*FD];

// ---------------- helpers ----------------
__device__ __forceinline__ float sigf(float x){
    x = fminf(fmaxf(x, -30.f), 30.f);
    return __fdividef(1.f, 1.f + __expf(-x));
}
__device__ __forceinline__ float tanhf_(float x){
    x = fminf(fmaxf(x, -15.f), 15.f);
    float e = __expf(2.f*x);
    return __fdividef(e - 1.f, e + 1.f);
}
__device__ __forceinline__ uint16_t f2e4m3x2(float lo, float hi){
    uint16_t r; asm("cvt.rn.satfinite.e4m3x2.f32 %0, %1, %2;" : "=h"(r) : "f"(hi), "f"(lo));
    return r;   // byte0 = lo, byte1 = hi
}
__device__ __forceinline__ uint8_t f2e4m3(float v){
    uint16_t r; asm("cvt.rn.satfinite.e4m3x2.f32 %0, %1, %2;" : "=h"(r) : "f"(0.f), "f"(v));
    return (uint8_t)r;
}
__device__ __forceinline__ void mma_f8(float* c, const uint32_t* a, const uint32_t* b){
    asm volatile(
        "mma.sync.aligned.m16n8k32.row.col.f32.e4m3.e4m3.f32 "
        "{%0,%1,%2,%3}, {%4,%5,%6,%7}, {%8,%9}, {%0,%1,%2,%3};"
        : "+f"(c[0]), "+f"(c[1]), "+f"(c[2]), "+f"(c[3])
        : "r"(a[0]), "r"(a[1]), "r"(a[2]), "r"(a[3]), "r"(b[0]), "r"(b[1]));
}
__device__ __forceinline__ void mma16816(float* c, const uint32_t* a, const uint32_t* b){
    asm volatile(
        "mma.sync.aligned.m16n8k16.row.col.f32.bf16.bf16.f32 "
        "{%0,%1,%2,%3}, {%4,%5,%6,%7}, {%8,%9}, {%0,%1,%2,%3};"
        : "+f"(c[0]), "+f"(c[1]), "+f"(c[2]), "+f"(c[3])
        : "r"(a[0]), "r"(a[1]), "r"(a[2]), "r"(a[3]), "r"(b[0]), "r"(b[1]));
}
__device__ __forceinline__ void ldsm4(uint32_t& r0, uint32_t& r1, uint32_t& r2, uint32_t& r3, uint32_t a){
    asm volatile("ldmatrix.sync.aligned.m8n8.x4.shared.b16 {%0,%1,%2,%3}, [%4];"
        : "=r"(r0), "=r"(r1), "=r"(r2), "=r"(r3) : "r"(a));
}
__device__ __forceinline__ void ldsm4t(uint32_t& r0, uint32_t& r1, uint32_t& r2, uint32_t& r3, uint32_t a){
    asm volatile("ldmatrix.sync.aligned.m8n8.x4.trans.shared.b16 {%0,%1,%2,%3}, [%4];"
        : "=r"(r0), "=r"(r1), "=r"(r2), "=r"(r3) : "r"(a));
}
__device__ __forceinline__ void cpasync16(uint32_t dst, const void* src){
    asm volatile("cp.async.cg.shared.global [%0], [%1], 16;\n" :: "r"(dst), "l"(src));
}
#define SWZ(off) ((off) ^ (((off) >> 3) & 0x70))

// ---------------- prep: conversions + gate permutation (forked stream) ----------------
// permuted gate index: cp = (u>>3)*32 + gate*8 + (u&7)
__global__ void __launch_bounds__(256) prep_conv(
    const float* __restrict__ x, const float* __restrict__ gw,
    const float* __restrict__ wih, const float* __restrict__ whh,
    const float* __restrict__ bih, const float* __restrict__ bhh,
    const float* __restrict__ fcw)
{
    int i = blockIdx.x*blockDim.x + threadIdx.x;
    int stride = gridDim.x*blockDim.x;
    for (int t = i; t < NN*FD; t += stride)    g_bx[t]   = __float2bfloat16_rn(x[t]);
    for (int t = i; t < KG*FD*HD; t += stride) g_bgw[t]  = __float2bfloat16_rn(gw[t]);
    for (int t = i; t < KG*FD*HD; t += stride) g_fcw8[t] = f2e4m3(16.f*fcw[t]);
    for (int t = i; t < KG*G4*HD; t += stride){
        int k = t / (G4*HD);
        int rem = t - k*(G4*HD);
        int cp = rem >> 8, h = rem & 255;
        int gate = (cp >> 3) & 3;
        int u = ((cp >> 5) << 3) | (cp & 7);
        int orig = k*G4*HD + (gate*256 + u)*HD + h;
        g_wihp8[t] = f2e4m3(16.f*wih[orig]);
        g_whhp8[t] = f2e4m3(16.f*whh[orig]);
    }
    for (int t = i; t < KG*G4; t += stride){
        int k = t >> 10, cp = t & 1023;
        int gate = (cp >> 3) & 3;
        int u = ((cp >> 5) << 3) | (cp & 7);
        g_bcomb[t] = bih[k*G4 + gate*256 + u] + bhh[k*G4 + gate*256 + u];
    }
}

// ---------------- adj pass (unified, reads adj ONCE): passthrough + fp8 planes (+I) + dinv ----------------
__global__ void __launch_bounds__(256) adj_pass(const int* __restrict__ adj,
                                                float* __restrict__ out_adj)
{
    int row = blockIdx.x;
    const int4* src = reinterpret_cast<const int4*>(adj + (size_t)row*NN*KG);
    float4* dst = reinterpret_cast<float4*>(out_adj + (size_t)row*NN*KG);
    int c0 = 0, c1 = 0, c2 = 0;
    #pragma unroll
    for (int it = 0; it < 4; it++){
        int jg = threadIdx.x + it*256;               // group of 4 j's
        int4 v0 = src[jg*3+0];
        int4 v1 = src[jg*3+1];
        int4 v2 = src[jg*3+2];
        dst[jg*3+0] = make_float4((float)v0.x,(float)v0.y,(float)v0.z,(float)v0.w);
        dst[jg*3+1] = make_float4((float)v1.x,(float)v1.y,(float)v1.z,(float)v1.w);
        dst[jg*3+2] = make_float4((float)v2.x,(float)v2.y,(float)v2.z,(float)v2.w);
        // e4m3: 1.0f = 0x38
        uint32_t q0 = (v0.x?0x38u:0u) | ((v0.w?0x38u:0u)<<8) | ((v1.z?0x38u:0u)<<16) | ((v2.y?0x38u:0u)<<24);
        uint32_t q1 = (v0.y?0x38u:0u) | ((v1.x?0x38u:0u)<<8) | ((v1.w?0x38u:0u)<<16) | ((v2.z?0x38u:0u)<<24);
        uint32_t q2 = (v0.z?0x38u:0u) | ((v1.y?0x38u:0u)<<8) | ((v2.x?0x38u:0u)<<16) | ((v2.w?0x38u:0u)<<24);
        size_t base = (size_t)row*NN + jg*4;
        *reinterpret_cast<uint32_t*>(&g_a8[base])                   = q0;
        *reinterpret_cast<uint32_t*>(&g_a8[(size_t)NN*NN + base])   = q1;
        *reinterpret_cast<uint32_t*>(&g_a8[(size_t)2*NN*NN + base]) = q2;
        c0 += (v0.x?1:0) + (v0.w?1:0) + (v1.z?1:0) + (v2.y?1:0);
        c1 += (v0.y?1:0) + (v1.x?1:0) + (v1.w?1:0) + (v2.z?1:0);
        c2 += (v0.z?1:0) + (v1.y?1:0) + (v2.x?1:0) + (v2.w?1:0);
    }
    __shared__ int sm[3];
    if (threadIdx.x < 3) sm[threadIdx.x] = 0;
    __syncthreads();
    c0 = __reduce_add_sync(0xffffffffu, c0);
    c1 = __reduce_add_sync(0xffffffffu, c1);
    c2 = __reduce_add_sync(0xffffffffu, c2);
    if ((threadIdx.x & 31) == 0){
        atomicAdd(&sm[0], c0); atomicAdd(&sm[1], c1); atomicAdd(&sm[2], c2);
    }
    __syncthreads();
    if (threadIdx.x < 3){
        // self-loop: 0->1.0(0x38), 1->2.0(0x40); exact in e4m3
        size_t d = (size_t)threadIdx.x*NN*NN + (size_t)row*NN + row;
        g_a8[d] = (g_a8[d] == 0x38) ? 0x40 : 0x38;
        float deg = (float)(sm[threadIdx.x] + 1);
        g_dinv[threadIdx.x*NN + row] = rsqrtf(deg);
    }
}

// ---------------- XW GEMM (bf16): s = dinv*x@gnn_w, stored TRANSPOSED as fp8(64*s) ----------------
__global__ void __launch_bounds__(256, 2) gemm_xw()
{
    __shared__ bf16 As[2][128*64];
    __shared__ bf16 Bs[2][64*64];
    int n0 = blockIdx.x*64, m0 = blockIdx.y*128, kb = blockIdx.z;
    const bf16* A = g_bx;
    const bf16* B = g_bgw + (size_t)kb*FD*HD;

    int tid = threadIdx.x, lane = tid & 31, wid = tid >> 5;
    int wm = wid & 3, wn = wid >> 2;
    uint32_t asB[2], bsB[2];
    asB[0] = (uint32_t)__cvta_generic_to_shared(&As[0][0]);
    asB[1] = (uint32_t)__cvta_generic_to_shared(&As[1][0]);
    bsB[0] = (uint32_t)__cvta_generic_to_shared(&Bs[0][0]);
    bsB[1] = (uint32_t)__cvta_generic_to_shared(&Bs[1][0]);

    float acc[2][4][4];
    #pragma unroll
    for (int a = 0; a < 2; a++)
        #pragma unroll
        for (int b = 0; b < 4; b++)
            #pragma unroll
            for (int e = 0; e < 4; e++) acc[a][b][e] = 0.f;

    // hoisted addressing
    const bf16* ap[4]; uint32_t ao[4];
    #pragma unroll
    for (int i = 0; i < 4; i++){
        int idx = tid + i*256;
        int row = idx >> 3, c = idx & 7;
        ap[i] = A + (size_t)(m0+row)*HD + c*8;
        ao[i] = SWZ(row*128 + c*16);
    }
    const bf16* bp[2]; uint32_t bo[2];
    #pragma unroll
    for (int i = 0; i < 2; i++){
        int idx = tid + i*256;
        int row = idx >> 3, c = idx & 7;
        bp[i] = B + (size_t)row*HD + n0 + c*8;
        bo[i] = SWZ(row*128 + c*16);
    }

    auto load_tile = [&](int kt, int s){
        #pragma unroll
        for (int i = 0; i < 4; i++) cpasync16(asB[s] + ao[i], ap[i] + kt*64);
        #pragma unroll
        for (int i = 0; i < 2; i++) cpasync16(bsB[s] + bo[i], bp[i] + (size_t)kt*64*HD);
        asm volatile("cp.async.commit_group;\n" ::: "memory");
    };

    load_tile(0, 0);
    int lr = lane & 15, lc = lane >> 4;
    for (int kt = 0; kt < 4; kt++){
        if (kt + 1 < 4){
            load_tile(kt+1, (kt+1)&1);
            asm volatile("cp.async.wait_group 1;\n" ::: "memory");
        } else {
            asm volatile("cp.async.wait_group 0;\n" ::: "memory");
        }
        __syncthreads();
        int s = kt & 1;
        #pragma unroll
        for (int k16 = 0; k16 < 4; k16++){
            uint32_t a[2][4];
            #pragma unroll
            for (int mt = 0; mt < 2; mt++){
                int row = wm*32 + mt*16 + lr;
                ldsm4(a[mt][0], a[mt][1], a[mt][2], a[mt][3], asB[s] + SWZ(row*128 + k16*32 + lc*16));
            }
            uint32_t b[4][2];
            #pragma unroll
            for (int p = 0; p < 2; p++){
                uint32_t r0, r1, r2, r3;
                int row = k16*16 + lr;
                ldsm4t(r0, r1, r2, r3, bsB[s] + SWZ(row*128 + (wn*32 + p*16 + lc*8)*2));
                b[p*2  ][0] = r0; b[p*2  ][1] = r1;
                b[p*2+1][0] = r2; b[p*2+1][1] = r3;
            }
            #pragma unroll
            for (int mt = 0; mt < 2; mt++)
                #pragma unroll
                for (int nt = 0; nt < 4; nt++)
                    mma16816(acc[mt][nt], a[mt], b[nt]);
        }
        __syncthreads();
    }

    int g = lane >> 2, t4 = lane & 3;
    #pragma unroll
    for (int mt = 0; mt < 2; mt++)
        #pragma unroll
        for (int nt = 0; nt < 4; nt++)
            #pragma unroll
            for (int rh = 0; rh < 2; rh++){
                int r = m0 + wm*32 + mt*16 + g + rh*8;
                int c = n0 + wn*32 + nt*8 + t4*2;
                float sc = 64.f * g_dinv[kb*NN + r];
                size_t tb = (size_t)kb*HD*NN;
                g_sT8[tb + (size_t)c*NN + r]     = f2e4m3(sc*acc[mt][nt][rh*2+0]);
                g_sT8[tb + (size_t)(c+1)*NN + r] = f2e4m3(sc*acc[mt][nt][rh*2+1]);
            }
}

// ---------------- fp8 epilogues ----------------
struct EpiGCN {
    const float* gb;
    __device__ void operator()(int k, int r, int c, float v0, float v1) const {
        float di = g_dinv[k*NN + r] * (1.f/64.f);
        size_t i = ((size_t)k*NN + r)*HD + c;
        *reinterpret_cast<uint16_t*>(&g_gnn8[i]) =
            f2e4m3x2(di*v0 + gb[k*HD + c], di*v1 + gb[k*HD + c + 1]);
    }
};
struct EpiFC {
    const float* fcb;
    __device__ void operator()(int k, int r, int c, float v0, float v1) const {
        size_t i = ((size_t)k*NN + r)*FD + c;
        g_delta[i]   = tanhf_(v0*(1.f/16.f) + fcb[k*FD + c]);
        g_delta[i+1] = tanhf_(v1*(1.f/16.f) + fcb[k*FD + c + 1]);
    }
};

// ---------------- fp8 GEMM: BM=128, BN=64, BK=128 bytes, double-buffered ----------------
// A row-major [M][KD] fp8; B n-major [NC][KD] fp8 (row = output col, bytes = k).
template<int KD, int NC, bool GORD, class Epi>
__global__ void __launch_bounds__(256, 2) gemm_f8(int a_sel, int b_sel, Epi epi)
{
    __shared__ uint8_t As[2][128*128];
    __shared__ uint8_t Bs[2][64*128];

    int n0, m0, kb;
    if (GORD){ n0 = blockIdx.x*64; kb = blockIdx.y; m0 = blockIdx.z*128; }
    else     { n0 = blockIdx.x*64; m0 = blockIdx.y*128; kb = blockIdx.z; }

    const uint8_t* A = (a_sel == 0) ? g_a8 + (size_t)kb*NN*NN
                                    : g_h8 + (size_t)kb*NN*HD;
    const uint8_t* B = (b_sel == 0) ? g_sT8 + (size_t)kb*HD*NN
                                    : g_fcw8 + (size_t)kb*FD*HD;

    int tid = threadIdx.x, lane = tid & 31, wid = tid >> 5;
    int wm = wid & 3, wn = wid >> 2;
    uint32_t asB[2], bsB[2];
    asB[0] = (uint32_t)__cvta_generic_to_shared(&As[0][0]);
    asB[1] = (uint32_t)__cvta_generic_to_shared(&As[1][0]);
    bsB[0] = (uint32_t)__cvta_generic_to_shared(&Bs[0][0]);
    bsB[1] = (uint32_t)__cvta_generic_to_shared(&Bs[1][0]);

    float acc[2][4][4];
    #pragma unroll
    for (int a = 0; a < 2; a++)
        #pragma unroll
        for (int b = 0; b < 4; b++)
            #pragma unroll
            for (int e = 0; e < 4; e++) acc[a][b][e] = 0.f;

    constexpr int KT = KD/128;

    // hoisted cp.async addressing (64-bit math out of the k-loop)
    const uint8_t* ap[4]; uint32_t ao[4];
    #pragma unroll
    for (int i = 0; i < 4; i++){
        int idx = tid + i*256;
        int row = idx >> 3, c = idx & 7;
        ap[i] = A + (size_t)(m0+row)*KD + c*16;
        ao[i] = SWZ(row*128 + c*16);
    }
    const uint8_t* bp[2]; uint32_t bo[2];
    #pragma unroll
    for (int i = 0; i < 2; i++){
        int idx = tid + i*256;
        int row = idx >> 3, c = idx & 7;
        bp[i] = B + (size_t)(n0+row)*KD + c*16;
        bo[i] = SWZ(row*128 + c*16);
    }

    auto load_tile = [&](int kt, int s){
        #pragma unroll
        for (int i = 0; i < 4; i++) cpasync16(asB[s] + ao[i], ap[i] + kt*128);
        #pragma unroll
        for (int i = 0; i < 2; i++) cpasync16(bsB[s] + bo[i], bp[i] + kt*128);
        asm volatile("cp.async.commit_group;\n" ::: "memory");
    };

    load_tile(0, 0);
    int lr = lane & 15, lc = lane >> 4;
    for (int kt = 0; kt < KT; kt++){
        if (kt + 1 < KT){
            load_tile(kt+1, (kt+1)&1);
            asm volatile("cp.async.wait_group 1;\n" ::: "memory");
        } else {
            asm volatile("cp.async.wait_group 0;\n" ::: "memory");
        }
        __syncthreads();
        int s = kt & 1;
        #pragma unroll
        for (int c32 = 0; c32 < 4; c32++){
            uint32_t a[2][4];
            #pragma unroll
            for (int mt = 0; mt < 2; mt++){
                int row = wm*32 + mt*16 + lr;
                ldsm4(a[mt][0], a[mt][1], a[mt][2], a[mt][3], asB[s] + SWZ(row*128 + c32*32 + lc*16));
            }
            uint32_t b[4][2];
            #pragma unroll
            for (int p = 0; p < 2; p++){
                uint32_t r0, r1, r2, r3;
                int row = wn*32 + p*16 + lr;
                ldsm4(r0, r1, r2, r3, bsB[s] + SWZ(row*128 + c32*32 + lc*16));
                b[p*2  ][0] = r0; b[p*2  ][1] = r2;
                b[p*2+1][0] = r1; b[p*2+1][1] = r3;
            }
            #pragma unroll
            for (int mt = 0; mt < 2; mt++)
                #pragma unroll
                for (int nt = 0; nt < 4; nt++)
                    mma_f8(acc[mt][nt], a[mt], b[nt]);
        }
        __syncthreads();
    }

    int g = lane >> 2, t4 = lane & 3;
    #pragma unroll
    for (int mt = 0; mt < 2; mt++)
        #pragma unroll
        for (int nt = 0; nt < 4; nt++){
            int r = m0 + wm*32 + mt*16 + g;
            int c = n0 + wn*32 + nt*8 + t4*2;
            epi(kb, r,     c, acc[mt][nt][0], acc[mt][nt][1]);
            epi(kb, r + 8, c, acc[mt][nt][2], acc[mt][nt][3]);
        }
}

// ---------------- fused fp8 LSTM GEMM + pointwise ----------------
template<bool FIRST>
__global__ void __launch_bounds__(256, 2) gemm_lstm()
{
    __shared__ uint8_t As[2][128*128];
    __shared__ uint8_t Bs[2][64*128];

    int n0 = blockIdx.x*64, m0 = blockIdx.y*128, kb = blockIdx.z;

    const uint8_t* A = (FIRST ? g_gnn8 : g_h8) + (size_t)kb*NN*HD;
    const uint8_t* B = (FIRST ? g_wihp8 : g_whhp8) + (size_t)kb*G4*HD;

    int tid = threadIdx.x, lane = tid & 31, wid = tid >> 5;
    int wm = wid & 3, wn = wid >> 2;
    uint32_t asB[2], bsB[2];
    asB[0] = (uint32_t)__cvta_generic_to_shared(&As[0][0]);
    asB[1] = (uint32_t)__cvta_generic_to_shared(&As[1][0]);
    bsB[0] = (uint32_t)__cvta_generic_to_shared(&Bs[0][0]);
    bsB[1] = (uint32_t)__cvta_generic_to_shared(&Bs[1][0]);

    float acc[2][4][4];
    #pragma unroll
    for (int a = 0; a < 2; a++)
        #pragma unroll
        for (int b = 0; b < 4; b++)
            #pragma unroll
            for (int e = 0; e < 4; e++) acc[a][b][e] = 0.f;

    // hoisted cp.async addressing
    const uint8_t* ap[4]; uint32_t ao[4];
    #pragma unroll
    for (int i = 0; i < 4; i++){
        int idx = tid + i*256;
        int row = idx >> 3, c = idx & 7;
        ap[i] = A + (size_t)(m0+row)*HD + c*16;
        ao[i] = SWZ(row*128 + c*16);
    }
    const uint8_t* bp[2]; uint32_t bo[2];
    #pragma unroll
    for (int i = 0; i < 2; i++){
        int idx = tid + i*256;
        int row = idx >> 3, c = idx & 7;
        bp[i] = B + (size_t)(n0+row)*HD + c*16;
        bo[i] = SWZ(row*128 + c*16);
    }

    auto load_tile = [&](int kt, int s){
        #pragma unroll
        for (int i = 0; i < 4; i++) cpasync16(asB[s] + ao[i], ap[i] + kt*128);
        #pragma unroll
        for (int i = 0; i < 2; i++) cpasync16(bsB[s] + bo[i], bp[i] + kt*128);
        asm volatile("cp.async.commit_group;\n" ::: "memory");
    };

    load_tile(0, 0);
    int lr = lane & 15, lc = lane >> 4;
    #pragma unroll
    for (int kt = 0; kt < 2; kt++){
        if (kt == 0){
            load_tile(1, 1);
            asm volatile("cp.async.wait_group 1;\n" ::: "memory");
        } else {
            asm volatile("cp.async.wait_group 0;\n" ::: "memory");
        }
        __syncthreads();
        int s = kt & 1;
        #pragma unroll
        for (int c32 = 0; c32 < 4; c32++){
            uint32_t a[2][4];
            #pragma unroll
            for (int mt = 0; mt < 2; mt++){
                int row = wm*32 + mt*16 + lr;
                ldsm4(a[mt][0], a[mt][1], a[mt][2], a[mt][3], asB[s] + SWZ(row*128 + c32*32 + lc*16));
            }
            uint32_t b[4][2];
            #pragma unroll
            for (int p = 0; p < 2; p++){
                uint32_t r0, r1, r2, r3;
                int row = wn*32 + p*16 + lr;
                ldsm4(r0, r1, r2, r3, bsB[s] + SWZ(row*128 + c32*32 + lc*16));
                b[p*2  ][0] = r0; b[p*2  ][1] = r2;
                b[p*2+1][0] = r1; b[p*2+1][1] = r3;
            }
            #pragma unroll
            for (int mt = 0; mt < 2; mt++)
                #pragma unroll
                for (int nt = 0; nt < 4; nt++)
                    mma_f8(acc[mt][nt], a[mt], b[nt]);
        }
        __syncthreads();
    }

    // ---- fused epilogue: gates -> (c, h) ----
    int g = lane >> 2, t4 = lane & 3;
    int group = (n0 + wn*32) >> 5;
    int ubase = group*8 + t4*2;                 // unit pair (ubase, ubase+1)
    #pragma unroll
    for (int mt = 0; mt < 2; mt++){
        #pragma unroll
        for (int rh = 0; rh < 2; rh++){
            int rr = m0 + wm*32 + mt*16 + g + rh*8;
            size_t xrow = ((size_t)kb*NN + rr)*G4 + n0 + wn*32 + t4*2;
            float gv[4][2];                     // [gate][unit01]
            #pragma unroll
            for (int nt = 0; nt < 4; nt++){
                float v0 = acc[mt][nt][rh*2+0] * (1.f/16.f);
                float v1 = acc[mt][nt][rh*2+1] * (1.f/16.f);
                if (FIRST){
                    const float2 bb = *reinterpret_cast<const float2*>(
                        &g_bcomb[kb*G4 + n0 + wn*32 + nt*8 + t4*2]);
                    v0 += bb.x; v1 += bb.y;
                    *reinterpret_cast<bf162*>(&g_xtp16[xrow + nt*8]) =
                        __floats2bfloat162_rn(v0, v1);
                } else {
                    bf162 xp = *reinterpret_cast<const bf162*>(&g_xtp16[xrow + nt*8]);
                    v0 += __bfloat162float(xp.x);
                    v1 += __bfloat162float(xp.y);
                }
                gv[nt][0] = v0; gv[nt][1] = v1;
            }
            size_t ci = ((size_t)kb*NN + rr)*HD + ubase;
            float c0_old = 0.f, c1_old = 0.f;
            if (!FIRST){
                float2 co = *reinterpret_cast<const float2*>(&g_c[ci]);
                c0_old = co.x; c1_old = co.y;
            }
            float cn0 = sigf(gv[1][0])*c0_old + sigf(gv[0][0])*tanhf_(gv[2][0]);
            float cn1 = sigf(gv[1][1])*c1_old + sigf(gv[0][1])*tanhf_(gv[2][1]);
            float hn0 = sigf(gv[3][0])*tanhf_(cn0);
            float hn1 = sigf(gv[3][1])*tanhf_(cn1);
            *reinterpret_cast<float2*>(&g_c[ci]) = make_float2(cn0, cn1);
            *reinterpret_cast<uint16_t*>(&g_h8[ci]) = f2e4m3x2(hn0, hn1);
        }
    }
}

// ---------------- final: pred + res_z_bar ----------------
__global__ void __launch_bounds__(256) final_out(const float* __restrict__ x,
                                                 float* __restrict__ out)
{
    int idx = blockIdx.x*256 + threadIdx.x;   // over NN*FD
    int f = idx & 255;
    bool sl = (f >= 10) && (f < FD - 3);      // START=10, F_DIM-END=253
    float xv = x[idx];
    float d0 = g_delta[idx];
    float d1 = g_delta[(size_t)NN*FD + idx];
    float d2 = g_delta[(size_t)2*NN*FD + idx];
    float z0 = xv + d0, z1 = xv + d1, z2 = xv + d2;
    if (sl){ z0 = sigf(z0); z1 = sigf(z1); z2 = sigf(z2); }
    size_t zb = (size_t)NN*FD + (size_t)idx*3;
    out[zb + 0] = z0; out[zb + 1] = z1; out[zb + 2] = z2;
    float dm = (d0 + d1 + d2) * (1.f/3.f);
    float p = xv + dm;
    if (sl) p = sigf(p);
    out[idx] = p;
}

// ---------------- stream/event resources (created once, first call is uncaptured) ----------------
struct AuxRes {
    cudaStream_t s2;
    cudaEvent_t e_root, e_prep;
    AuxRes(){
        cudaStreamCreateWithFlags(&s2, cudaStreamNonBlocking);
        cudaEventCreateWithFlags(&e_root, cudaEventDisableTiming);
        cudaEventCreateWithFlags(&e_prep, cudaEventDisableTiming);
    }
};

// ---------------- launch ----------------
extern "C" void kernel_launch(void* const* d_in, const int* in_sizes, int n_in,
                              void* d_out, int out_size)
{
    const float* x     = (const float*)d_in[0];
    const float* gnn_w = (const float*)d_in[1];
    const float* gnn_b = (const float*)d_in[2];
    const float* w_ih  = (const float*)d_in[3];
    const float* w_hh  = (const float*)d_in[4];
    const float* b_ih  = (const float*)d_in[5];
    const float* b_hh  = (const float*)d_in[6];
    const float* fc_w  = (const float*)d_in[7];
    const float* fc_b  = (const float*)d_in[8];
    const int*   adj   = (const int*)d_in[9];
    float* out = (float*)d_out;

    (void)in_sizes; (void)n_in; (void)out_size;

    static AuxRes R;   // one-time resource creation (first call precedes capture)

    // fork: prep_conv (tiny DRAM footprint) overlaps the DRAM-bound adj_pass
    cudaEventRecord(R.e_root, 0);
    cudaStreamWaitEvent(R.s2, R.e_root, 0);
    prep_conv<<<512, 256, 0, R.s2>>>(x, gnn_w, w_ih, w_hh, b_ih, b_hh, fc_w);
    cudaEventRecord(R.e_prep, R.s2);

    // main stream: adj read ONCE -> float passthrough + fp8 planes + dinv
    adj_pass<<<NN, 256>>>(adj, out + (size_t)NN*FD*(1 + KG));

    // join prep before the GEMM chain
    cudaStreamWaitEvent(0, R.e_prep, 0);

    // sT8[h][j] = fp8(64 * dinv_j * (x @ gnn_w)[j][h])   (bf16 GEMM)
    gemm_xw<<<dim3(4, 32, 3), 256>>>();
    // gnn_out[k] = dinv_i * ((A+I) @ s)/64 + b           (fp8 GEMM, grid n,k,m for L2 A reuse)
    gemm_f8<4096, 256, true, EpiGCN><<<dim3(4, 3, 32), 256>>>(0, 0, EpiGCN{gnn_b});
    // xtp = gnn @ (16 Wp_ih)^T /16 + b, fused LSTM step 1
    gemm_lstm<true><<<dim3(16, 32, 3), 256>>>();
    // steps 2..5: gates = h @ (16 Wp_hh)^T /16 + xtp, fused pointwise
    for (int t = 1; t < TST; t++)
        gemm_lstm<false><<<dim3(16, 32, 3), 256>>>();
    // delta = tanh(h @ (16 fc_w)^T /16 + fc_b)
    gemm_f8<256, 256, false, EpiFC><<<dim3(4, 32, 3), 256>>>(1, 1, EpiFC{fc_b});
    final_out<<<NN*FD/256, 256>>>(x, out);
}